// round 1
// baseline (speedup 1.0000x reference)
#include <cuda_runtime.h>
#include <math.h>

// Model dims
#define BBATCH 4
#define TSEQ   512
#define BT     2048      // BBATCH*TSEQ
#define DMODEL 1024
#define NHEAD  16
#define HDIM   64
#define FINNER 4096
#define VOCAB  32000
#define NLAYER 8

// ---------------- scratch (no allocations allowed) ----------------
__device__ float g_h  [BT * DMODEL];
__device__ float g_x  [BT * DMODEL];
__device__ float g_q  [BT * DMODEL];
__device__ float g_k  [BT * DMODEL];
__device__ float g_v  [BT * DMODEL];
__device__ float g_o  [BT * DMODEL];
__device__ float g_tmp[BT * DMODEL];
__device__ float g_ff [BT * FINNER];
__device__ float g_sc [(size_t)BBATCH * NHEAD * TSEQ * TSEQ]; // 67 MB
__device__ float g_enc[4 * BT * DMODEL];
__device__ float g_wot[NLAYER * DMODEL * DMODEL];             // repacked Wo*gate
__device__ float g_bos[NLAYER * DMODEL];                      // gate-reduced bo

// ---------------- prep: repack Wo with gate folded in ----------------
// wot[l][d][c] = Wo[l][c/64][d][c%64] * gate[l][c/64]
__global__ void prep_wot(const float* __restrict__ Wo, const float* __restrict__ gate,
                         float* __restrict__ wot) {
    long idx = (long)blockIdx.x * 256 + threadIdx.x;
    if (idx >= (long)NLAYER * DMODEL * DMODEL) return;
    int l = (int)(idx >> 20);
    int d = (int)((idx >> 10) & 1023);
    int c = (int)(idx & 1023);
    int n = c >> 6, hh = c & 63;
    wot[idx] = Wo[((long)(l * NHEAD + n)) * (DMODEL * HDIM) + (long)d * HDIM + hh]
             * gate[l * NHEAD + n];
}

// bos[l][d] = sum_n gate[l][n] * bo[l][n][d]
__global__ void prep_bos(const float* __restrict__ bo, const float* __restrict__ gate,
                         float* __restrict__ bos) {
    int idx = blockIdx.x * 256 + threadIdx.x;
    if (idx >= NLAYER * DMODEL) return;
    int l = idx >> 10, d = idx & 1023;
    float s = 0.f;
    for (int n = 0; n < NHEAD; n++)
        s += gate[l * NHEAD + n] * bo[(long)(l * NHEAD + n) * DMODEL + d];
    bos[idx] = s;
}

// ---------------- embedding ----------------
__global__ void embed_k(const int* __restrict__ ids, const float* __restrict__ wte,
                        const float* __restrict__ wpe, float* __restrict__ h) {
    long idx = (long)blockIdx.x * 256 + threadIdx.x;
    if (idx >= (long)BT * DMODEL) return;
    int bt = (int)(idx >> 10), d = (int)(idx & 1023);
    int t = bt & (TSEQ - 1);
    h[idx] = wte[(long)ids[bt] * DMODEL + d] + wpe[(long)t * DMODEL + d];
}

// ---------------- layernorm (one block per row) ----------------
__global__ void layernorm_k(const float* __restrict__ in, float* __restrict__ out,
                            const float* __restrict__ g, const float* __restrict__ b) {
    int row = blockIdx.x;
    const float* x = in + (long)row * DMODEL;
    float* y = out + (long)row * DMODEL;
    __shared__ float red[256];
    int tid = threadIdx.x;
    float s = 0.f;
    for (int i = tid; i < DMODEL; i += 256) s += x[i];
    red[tid] = s; __syncthreads();
    for (int o = 128; o > 0; o >>= 1) { if (tid < o) red[tid] += red[tid + o]; __syncthreads(); }
    float mean = red[0] * (1.0f / DMODEL);
    __syncthreads();
    float v = 0.f;
    for (int i = tid; i < DMODEL; i += 256) { float d = x[i] - mean; v += d * d; }
    red[tid] = v; __syncthreads();
    for (int o = 128; o > 0; o >>= 1) { if (tid < o) red[tid] += red[tid + o]; __syncthreads(); }
    float inv = rsqrtf(red[0] * (1.0f / DMODEL) + 1e-5f);
    for (int i = tid; i < DMODEL; i += 256)
        y[i] = (x[i] - mean) * inv * g[i] + b[i];
}

// ---------------- generic NT GEMM: C = A[M,K] * B[N,K]^T (+bias)(+res)(gelu) ----
// 128x128x8 tile, 8x8 microtile, 256 threads, strided (tx+16j) column mapping.
// All callers use exact tile multiples — no bounds guards.
template<int EPI, bool BIAS, bool RES>
__global__ __launch_bounds__(256) void gemm128(
    const float* __restrict__ A, const float* __restrict__ Bm,
    const float* __restrict__ bias, const float* __restrict__ res,
    float* __restrict__ C, int M, int N, int K, int lda, int ldb, int ldc) {
    __shared__ float As[8][128];
    __shared__ float Bs[8][132];
    int tid = threadIdx.x;
    int tx = tid & 15, ty = tid >> 4;
    int m0 = blockIdx.y * 128, n0 = blockIdx.x * 128;
    const float* Ap = A + (long)m0 * lda;
    const float* Bp = Bm + (long)n0 * ldb;
    float acc[8][8];
    #pragma unroll
    for (int i = 0; i < 8; i++)
        #pragma unroll
        for (int j = 0; j < 8; j++) acc[i][j] = 0.f;

    for (int k0 = 0; k0 < K; k0 += 8) {
        #pragma unroll
        for (int i = 0; i < 4; i++) {
            int e = tid + i * 256;
            int r = e >> 3, c = e & 7;
            As[c][r] = Ap[(long)r * lda + k0 + c];
            Bs[c][r] = Bp[(long)r * ldb + k0 + c];
        }
        __syncthreads();
        #pragma unroll
        for (int kk = 0; kk < 8; kk++) {
            float a[8], bb[8];
            #pragma unroll
            for (int i = 0; i < 8; i++) a[i]  = As[kk][ty + 16 * i];
            #pragma unroll
            for (int j = 0; j < 8; j++) bb[j] = Bs[kk][tx + 16 * j];
            #pragma unroll
            for (int i = 0; i < 8; i++)
                #pragma unroll
                for (int j = 0; j < 8; j++) acc[i][j] += a[i] * bb[j];
        }
        __syncthreads();
    }
    #pragma unroll
    for (int i = 0; i < 8; i++) {
        int m = m0 + ty + 16 * i;
        #pragma unroll
        for (int j = 0; j < 8; j++) {
            int n = n0 + tx + 16 * j;
            float v = acc[i][j];
            if (BIAS) v += bias[n];
            if (RES)  v += res[(long)m * ldc + n];
            if (EPI == 2) v = 0.5f * v * (1.0f + erff(v * 0.70710678118654752f));
            C[(long)m * ldc + n] = v;
        }
    }
}

// ---------------- attention: scores = scale * Q Khead^T (causal-tile skip) ----
__global__ __launch_bounds__(256) void attn_scores(
    const float* __restrict__ Q, const float* __restrict__ Km, float* __restrict__ S) {
    int bh = blockIdx.z;
    int b = bh >> 4, n = bh & 15;
    int s0 = blockIdx.x * 64, t0 = blockIdx.y * 64;
    if (s0 > t0) return; // fully masked tile
    __shared__ float Qs[64][65];
    __shared__ float Ks[64][65];
    int tid = threadIdx.x;
    const float* Qp = Q + ((long)(b * TSEQ + t0)) * DMODEL + n * HDIM;
    const float* Kp = Km + ((long)(b * TSEQ + s0)) * DMODEL + n * HDIM;
    #pragma unroll
    for (int i = 0; i < 16; i++) {
        int e = tid + i * 256;
        int r = e >> 6, c = e & 63;
        Qs[r][c] = Qp[(long)r * DMODEL + c];
        Ks[r][c] = Kp[(long)r * DMODEL + c];
    }
    __syncthreads();
    int tx = tid & 15, ty = tid >> 4;
    float acc[4][4];
    #pragma unroll
    for (int i = 0; i < 4; i++)
        #pragma unroll
        for (int j = 0; j < 4; j++) acc[i][j] = 0.f;
    #pragma unroll 8
    for (int k = 0; k < 64; k++) {
        float a[4], bb[4];
        #pragma unroll
        for (int i = 0; i < 4; i++) a[i]  = Qs[ty + 16 * i][k];
        #pragma unroll
        for (int j = 0; j < 4; j++) bb[j] = Ks[tx + 16 * j][k];
        #pragma unroll
        for (int i = 0; i < 4; i++)
            #pragma unroll
            for (int j = 0; j < 4; j++) acc[i][j] += a[i] * bb[j];
    }
    float* Sp = S + ((long)bh * TSEQ + t0) * TSEQ + s0;
    #pragma unroll
    for (int i = 0; i < 4; i++)
        #pragma unroll
        for (int j = 0; j < 4; j++)
            Sp[(long)(ty + 16 * i) * TSEQ + tx + 16 * j] = acc[i][j] * 0.125f;
}

// ---------------- causal softmax, zero-fill s>t ----------------
__global__ void softmax_rows(float* __restrict__ S) {
    int t = blockIdx.x, bh = blockIdx.y;
    float* row = S + ((long)bh * TSEQ + t) * TSEQ;
    int len = t + 1;
    __shared__ float red[128];
    int tid = threadIdx.x;
    float mx = -1e30f;
    for (int s = tid; s < len; s += 128) mx = fmaxf(mx, row[s]);
    red[tid] = mx; __syncthreads();
    for (int o = 64; o > 0; o >>= 1) { if (tid < o) red[tid] = fmaxf(red[tid], red[tid + o]); __syncthreads(); }
    mx = red[0]; __syncthreads();
    float sum = 0.f;
    for (int s = tid; s < len; s += 128) { float e = __expf(row[s] - mx); row[s] = e; sum += e; }
    red[tid] = sum; __syncthreads();
    for (int o = 64; o > 0; o >>= 1) { if (tid < o) red[tid] += red[tid + o]; __syncthreads(); }
    float inv = 1.0f / red[0];
    for (int s = tid; s < len; s += 128) row[s] *= inv;
    for (int s = len + tid; s < TSEQ; s += 128) row[s] = 0.0f;
}

// ---------------- attention: O = P * Vhead ----------------
__global__ __launch_bounds__(256) void attn_pv(
    const float* __restrict__ P, const float* __restrict__ V, float* __restrict__ O) {
    int bh = blockIdx.y;
    int b = bh >> 4, n = bh & 15;
    int t0 = blockIdx.x * 64;
    __shared__ float Ps[32][68];
    __shared__ float Vs[32][64];
    int tid = threadIdx.x;
    int tx = tid & 15, ty = tid >> 4;
    const float* Pp = P + ((long)bh * TSEQ + t0) * TSEQ;
    const float* Vp = V + (long)b * TSEQ * DMODEL + n * HDIM;
    float acc[4][4];
    #pragma unroll
    for (int i = 0; i < 4; i++)
        #pragma unroll
        for (int j = 0; j < 4; j++) acc[i][j] = 0.f;
    int kmax = t0 + 64; // P rows in this tile are zero beyond t0+63
    for (int k0 = 0; k0 < kmax; k0 += 32) {
        #pragma unroll
        for (int i = 0; i < 8; i++) {
            int e = tid + i * 256;
            int r = e >> 5, c = e & 31;       // P: (t=r, k=c)
            Ps[c][r] = Pp[(long)r * TSEQ + k0 + c];
        }
        #pragma unroll
        for (int i = 0; i < 8; i++) {
            int e = tid + i * 256;
            int r = e >> 6, c = e & 63;       // V: (k=r, h=c)
            Vs[r][c] = Vp[(long)(k0 + r) * DMODEL + c];
        }
        __syncthreads();
        #pragma unroll
        for (int kk = 0; kk < 32; kk++) {
            float a[4], bb[4];
            #pragma unroll
            for (int i = 0; i < 4; i++) a[i]  = Ps[kk][ty + 16 * i];
            #pragma unroll
            for (int j = 0; j < 4; j++) bb[j] = Vs[kk][tx + 16 * j];
            #pragma unroll
            for (int i = 0; i < 4; i++)
                #pragma unroll
                for (int j = 0; j < 4; j++) acc[i][j] += a[i] * bb[j];
        }
        __syncthreads();
    }
    #pragma unroll
    for (int i = 0; i < 4; i++)
        #pragma unroll
        for (int j = 0; j < 4; j++)
            O[(long)(b * TSEQ + t0 + ty + 16 * i) * DMODEL + n * HDIM + tx + 16 * j] = acc[i][j];
}

// ---------------- orchestration ----------------
extern "C" void kernel_launch(void* const* d_in, const int* in_sizes, int n_in,
                              void* d_out, int out_size) {
    const int*   ids  = (const int*)d_in[0];
    const float* wte  = (const float*)d_in[1];
    const float* wpe  = (const float*)d_in[2];
    const float* Wq   = (const float*)d_in[3];
    const float* bq   = (const float*)d_in[4];
    const float* Wk   = (const float*)d_in[5];
    const float* bk   = (const float*)d_in[6];
    const float* Wv   = (const float*)d_in[7];
    const float* bv   = (const float*)d_in[8];
    const float* Wo   = (const float*)d_in[9];
    const float* bo   = (const float*)d_in[10];
    const float* gate = (const float*)d_in[11];
    const float* ln1g = (const float*)d_in[12];
    const float* ln1b = (const float*)d_in[13];
    const float* ln2g = (const float*)d_in[14];
    const float* ln2b = (const float*)d_in[15];
    const float* w1   = (const float*)d_in[16];
    const float* b1   = (const float*)d_in[17];
    const float* w2   = (const float*)d_in[18];
    const float* b2   = (const float*)d_in[19];
    const float* skw  = (const float*)d_in[20];
    const float* skb  = (const float*)d_in[21];
    const float* lnfg = (const float*)d_in[22];
    const float* lnfb = (const float*)d_in[23];
    float* out = (float*)d_out;

    float *h, *x, *q, *k, *v, *o, *tmp, *ff, *sc, *enc, *wot, *bos;
    cudaGetSymbolAddress((void**)&h,   g_h);
    cudaGetSymbolAddress((void**)&x,   g_x);
    cudaGetSymbolAddress((void**)&q,   g_q);
    cudaGetSymbolAddress((void**)&k,   g_k);
    cudaGetSymbolAddress((void**)&v,   g_v);
    cudaGetSymbolAddress((void**)&o,   g_o);
    cudaGetSymbolAddress((void**)&tmp, g_tmp);
    cudaGetSymbolAddress((void**)&ff,  g_ff);
    cudaGetSymbolAddress((void**)&sc,  g_sc);
    cudaGetSymbolAddress((void**)&enc, g_enc);
    cudaGetSymbolAddress((void**)&wot, g_wot);
    cudaGetSymbolAddress((void**)&bos, g_bos);

    prep_wot<<<(NLAYER * DMODEL * DMODEL + 255) / 256, 256>>>(Wo, gate, wot);
    prep_bos<<<(NLAYER * DMODEL + 255) / 256, 256>>>(bo, gate, bos);
    embed_k<<<(BT * DMODEL + 255) / 256, 256>>>(ids, wte, wpe, h);

    dim3 gD(DMODEL / 128, BT / 128);   // N=1024 GEMMs
    dim3 gF(FINNER / 128, BT / 128);   // N=4096
    dim3 gV(VOCAB / 128, BT / 128);    // N=32000

    for (int i = 0; i < NLAYER; i++) {
        const float* Wq_l = Wq + (long)i * DMODEL * DMODEL;
        const float* Wk_l = Wk + (long)i * DMODEL * DMODEL;
        const float* Wv_l = Wv + (long)i * DMODEL * DMODEL;

        layernorm_k<<<BT, 256>>>(h, x, ln1g + i * DMODEL, ln1b + i * DMODEL);
        gemm128<0, true, false><<<gD, 256>>>(x, Wq_l, bq + i * DMODEL, nullptr, q,
                                             BT, DMODEL, DMODEL, DMODEL, DMODEL, DMODEL);
        gemm128<0, true, false><<<gD, 256>>>(x, Wk_l, bk + i * DMODEL, nullptr, k,
                                             BT, DMODEL, DMODEL, DMODEL, DMODEL, DMODEL);
        gemm128<0, true, false><<<gD, 256>>>(x, Wv_l, bv + i * DMODEL, nullptr, v,
                                             BT, DMODEL, DMODEL, DMODEL, DMODEL, DMODEL);

        attn_scores<<<dim3(TSEQ / 64, TSEQ / 64, BBATCH * NHEAD), 256>>>(q, k, sc);
        softmax_rows<<<dim3(TSEQ, BBATCH * NHEAD), 128>>>(sc);
        attn_pv<<<dim3(TSEQ / 64, BBATCH * NHEAD), 256>>>(sc, v, o);

        // h += o @ Wot^T + bos
        gemm128<0, true, true><<<gD, 256>>>(o, wot + (long)i * DMODEL * DMODEL,
                                            bos + i * DMODEL, h, h,
                                            BT, DMODEL, DMODEL, DMODEL, DMODEL, DMODEL);
        if (i < NLAYER / 2)
            cudaMemcpyAsync(enc + (long)i * BT * DMODEL, h,
                            (size_t)BT * DMODEL * sizeof(float), cudaMemcpyDeviceToDevice);

        layernorm_k<<<BT, 256>>>(h, x, ln2g + i * DMODEL, ln2b + i * DMODEL);
        // ff = gelu(x @ w1^T + b1)
        gemm128<2, true, false><<<gF, 256>>>(x, w1 + (long)i * FINNER * DMODEL,
                                             b1 + i * FINNER, nullptr, ff,
                                             BT, FINNER, DMODEL, DMODEL, DMODEL, FINNER);
        // h += ff @ w2^T + b2
        gemm128<0, true, true><<<gD, 256>>>(ff, w2 + (long)i * DMODEL * FINNER,
                                            b2 + i * DMODEL, h, h,
                                            BT, DMODEL, FINNER, FINNER, FINNER, DMODEL);

        if (i >= NLAYER / 2) {
            int el = NLAYER - i - 1;
            const float* sw = skw + (long)i * DMODEL * 2 * DMODEL;
            // tmp = h @ sw[:, :D]^T + skb
            gemm128<0, true, false><<<gD, 256>>>(h, sw, skb + i * DMODEL, nullptr, tmp,
                                                 BT, DMODEL, DMODEL, DMODEL, 2 * DMODEL, DMODEL);
            // h = tmp + enc[el] @ sw[:, D:]^T
            gemm128<0, false, true><<<gD, 256>>>(enc + (long)el * BT * DMODEL, sw + DMODEL,
                                                 nullptr, tmp, h,
                                                 BT, DMODEL, DMODEL, DMODEL, 2 * DMODEL, DMODEL);
        }
    }

    layernorm_k<<<BT, 256>>>(h, x, lnfg, lnfb);
    // logits = x @ wte^T
    gemm128<0, false, false><<<gV, 256>>>(x, wte, nullptr, nullptr, out,
                                          BT, VOCAB, DMODEL, DMODEL, DMODEL, VOCAB);
}

// round 2
// speedup vs baseline: 1.0527x; 1.0527x over previous
#include <cuda_runtime.h>
#include <math.h>

// Model dims
#define BBATCH 4
#define TSEQ   512
#define BT     2048      // BBATCH*TSEQ
#define DMODEL 1024
#define NHEAD  16
#define HDIM   64
#define FINNER 4096
#define VOCAB  32000
#define NLAYER 8

// ---------------- scratch (no allocations allowed) ----------------
__device__ float g_h  [BT * DMODEL];
__device__ float g_x  [BT * DMODEL];
__device__ float g_q  [BT * DMODEL];
__device__ float g_k  [BT * DMODEL];
__device__ float g_v  [BT * DMODEL];
__device__ float g_o  [BT * DMODEL];
__device__ float g_tmp[BT * DMODEL];
__device__ float g_ff [BT * FINNER];
__device__ float g_sc [(size_t)BBATCH * NHEAD * TSEQ * TSEQ]; // 67 MB
__device__ float g_enc[4 * BT * DMODEL];
__device__ float g_wot[NLAYER * DMODEL * DMODEL];             // repacked Wo*gate
__device__ float g_bos[NLAYER * DMODEL];                      // gate-reduced bo

// ---------------- prep: repack Wo with gate folded in ----------------
// wot[l][d][c] = Wo[l][c/64][d][c%64] * gate[l][c/64]
__global__ void prep_wot(const float* __restrict__ Wo, const float* __restrict__ gate,
                         float* __restrict__ wot) {
    long idx = (long)blockIdx.x * 256 + threadIdx.x;
    if (idx >= (long)NLAYER * DMODEL * DMODEL) return;
    int l = (int)(idx >> 20);
    int d = (int)((idx >> 10) & 1023);
    int c = (int)(idx & 1023);
    int n = c >> 6, hh = c & 63;
    wot[idx] = Wo[((long)(l * NHEAD + n)) * (DMODEL * HDIM) + (long)d * HDIM + hh]
             * gate[l * NHEAD + n];
}

// bos[l][d] = sum_n gate[l][n] * bo[l][n][d]
__global__ void prep_bos(const float* __restrict__ bo, const float* __restrict__ gate,
                         float* __restrict__ bos) {
    int idx = blockIdx.x * 256 + threadIdx.x;
    if (idx >= NLAYER * DMODEL) return;
    int l = idx >> 10, d = idx & 1023;
    float s = 0.f;
    for (int n = 0; n < NHEAD; n++)
        s += gate[l * NHEAD + n] * bo[(long)(l * NHEAD + n) * DMODEL + d];
    bos[idx] = s;
}

// ---------------- embedding ----------------
__global__ void embed_k(const int* __restrict__ ids, const float* __restrict__ wte,
                        const float* __restrict__ wpe, float* __restrict__ h) {
    long idx = (long)blockIdx.x * 256 + threadIdx.x;
    if (idx >= (long)BT * DMODEL) return;
    int bt = (int)(idx >> 10), d = (int)(idx & 1023);
    int t = bt & (TSEQ - 1);
    h[idx] = wte[(long)ids[bt] * DMODEL + d] + wpe[(long)t * DMODEL + d];
}

// ---------------- layernorm (one block per row) ----------------
__global__ void layernorm_k(const float* __restrict__ in, float* __restrict__ out,
                            const float* __restrict__ g, const float* __restrict__ b) {
    int row = blockIdx.x;
    const float* x = in + (long)row * DMODEL;
    float* y = out + (long)row * DMODEL;
    __shared__ float red[256];
    int tid = threadIdx.x;
    float s = 0.f;
    for (int i = tid; i < DMODEL; i += 256) s += x[i];
    red[tid] = s; __syncthreads();
    for (int o = 128; o > 0; o >>= 1) { if (tid < o) red[tid] += red[tid + o]; __syncthreads(); }
    float mean = red[0] * (1.0f / DMODEL);
    __syncthreads();
    float v = 0.f;
    for (int i = tid; i < DMODEL; i += 256) { float d = x[i] - mean; v += d * d; }
    red[tid] = v; __syncthreads();
    for (int o = 128; o > 0; o >>= 1) { if (tid < o) red[tid] += red[tid + o]; __syncthreads(); }
    float inv = rsqrtf(red[0] * (1.0f / DMODEL) + 1e-5f);
    for (int i = tid; i < DMODEL; i += 256)
        y[i] = (x[i] - mean) * inv * g[i] + b[i];
}

// ---------------- generic NT GEMM: C = A[M,K] * B[N,K]^T (+bias)(+res)(gelu) ----
// 128x128x8 tile, 8x8 microtile, 256 threads, strided (tx+16j) column mapping.
// All callers use exact tile multiples — no bounds guards.
template<int EPI, bool BIAS, bool RES>
__global__ __launch_bounds__(256) void gemm128(
    const float* __restrict__ A, const float* __restrict__ Bm,
    const float* __restrict__ bias, const float* __restrict__ res,
    float* __restrict__ C, int M, int N, int K, int lda, int ldb, int ldc) {
    __shared__ float As[8][128];
    __shared__ float Bs[8][132];
    int tid = threadIdx.x;
    int tx = tid & 15, ty = tid >> 4;
    int m0 = blockIdx.y * 128, n0 = blockIdx.x * 128;
    const float* Ap = A + (long)m0 * lda;
    const float* Bp = Bm + (long)n0 * ldb;
    float acc[8][8];
    #pragma unroll
    for (int i = 0; i < 8; i++)
        #pragma unroll
        for (int j = 0; j < 8; j++) acc[i][j] = 0.f;

    for (int k0 = 0; k0 < K; k0 += 8) {
        #pragma unroll
        for (int i = 0; i < 4; i++) {
            int e = tid + i * 256;
            int r = e >> 3, c = e & 7;
            As[c][r] = Ap[(long)r * lda + k0 + c];
            Bs[c][r] = Bp[(long)r * ldb + k0 + c];
        }
        __syncthreads();
        #pragma unroll
        for (int kk = 0; kk < 8; kk++) {
            float a[8], bb[8];
            #pragma unroll
            for (int i = 0; i < 8; i++) a[i]  = As[kk][ty + 16 * i];
            #pragma unroll
            for (int j = 0; j < 8; j++) bb[j] = Bs[kk][tx + 16 * j];
            #pragma unroll
            for (int i = 0; i < 8; i++)
                #pragma unroll
                for (int j = 0; j < 8; j++) acc[i][j] += a[i] * bb[j];
        }
        __syncthreads();
    }
    #pragma unroll
    for (int i = 0; i < 8; i++) {
        int m = m0 + ty + 16 * i;
        #pragma unroll
        for (int j = 0; j < 8; j++) {
            int n = n0 + tx + 16 * j;
            float v = acc[i][j];
            if (BIAS) v += bias[n];
            if (RES)  v += res[(long)m * ldc + n];
            if (EPI == 2) v = 0.5f * v * (1.0f + erff(v * 0.70710678118654752f));
            C[(long)m * ldc + n] = v;
        }
    }
}

// ---------------- attention: scores = scale * Q Khead^T (causal-tile skip) ----
__global__ __launch_bounds__(256) void attn_scores(
    const float* __restrict__ Q, const float* __restrict__ Km, float* __restrict__ S) {
    int bh = blockIdx.z;
    int b = bh >> 4, n = bh & 15;
    int s0 = blockIdx.x * 64, t0 = blockIdx.y * 64;
    if (s0 > t0) return; // fully masked tile
    __shared__ float Qs[64][65];
    __shared__ float Ks[64][65];
    int tid = threadIdx.x;
    const float* Qp = Q + ((long)(b * TSEQ + t0)) * DMODEL + n * HDIM;
    const float* Kp = Km + ((long)(b * TSEQ + s0)) * DMODEL + n * HDIM;
    #pragma unroll
    for (int i = 0; i < 16; i++) {
        int e = tid + i * 256;
        int r = e >> 6, c = e & 63;
        Qs[r][c] = Qp[(long)r * DMODEL + c];
        Ks[r][c] = Kp[(long)r * DMODEL + c];
    }
    __syncthreads();
    int tx = tid & 15, ty = tid >> 4;
    float acc[4][4];
    #pragma unroll
    for (int i = 0; i < 4; i++)
        #pragma unroll
        for (int j = 0; j < 4; j++) acc[i][j] = 0.f;
    #pragma unroll 8
    for (int k = 0; k < 64; k++) {
        float a[4], bb[4];
        #pragma unroll
        for (int i = 0; i < 4; i++) a[i]  = Qs[ty + 16 * i][k];
        #pragma unroll
        for (int j = 0; j < 4; j++) bb[j] = Ks[tx + 16 * j][k];
        #pragma unroll
        for (int i = 0; i < 4; i++)
            #pragma unroll
            for (int j = 0; j < 4; j++) acc[i][j] += a[i] * bb[j];
    }
    float* Sp = S + ((long)bh * TSEQ + t0) * TSEQ + s0;
    #pragma unroll
    for (int i = 0; i < 4; i++)
        #pragma unroll
        for (int j = 0; j < 4; j++)
            Sp[(long)(ty + 16 * i) * TSEQ + tx + 16 * j] = acc[i][j] * 0.125f;
}

// ---------------- causal softmax, zero-fill s>t ----------------
__global__ void softmax_rows(float* __restrict__ S) {
    int t = blockIdx.x, bh = blockIdx.y;
    float* row = S + ((long)bh * TSEQ + t) * TSEQ;
    int len = t + 1;
    __shared__ float red[128];
    int tid = threadIdx.x;
    float mx = -1e30f;
    for (int s = tid; s < len; s += 128) mx = fmaxf(mx, row[s]);
    red[tid] = mx; __syncthreads();
    for (int o = 64; o > 0; o >>= 1) { if (tid < o) red[tid] = fmaxf(red[tid], red[tid + o]); __syncthreads(); }
    mx = red[0]; __syncthreads();
    float sum = 0.f;
    for (int s = tid; s < len; s += 128) { float e = __expf(row[s] - mx); row[s] = e; sum += e; }
    red[tid] = sum; __syncthreads();
    for (int o = 64; o > 0; o >>= 1) { if (tid < o) red[tid] += red[tid + o]; __syncthreads(); }
    float inv = 1.0f / red[0];
    for (int s = tid; s < len; s += 128) row[s] *= inv;
    for (int s = len + tid; s < TSEQ; s += 128) row[s] = 0.0f;
}

// ---------------- attention: O = P * Vhead ----------------
__global__ __launch_bounds__(256) void attn_pv(
    const float* __restrict__ P, const float* __restrict__ V, float* __restrict__ O) {
    int bh = blockIdx.y;
    int b = bh >> 4, n = bh & 15;
    int t0 = blockIdx.x * 64;
    __shared__ float Ps[32][68];
    __shared__ float Vs[32][64];
    int tid = threadIdx.x;
    int tx = tid & 15, ty = tid >> 4;
    const float* Pp = P + ((long)bh * TSEQ + t0) * TSEQ;
    const float* Vp = V + (long)b * TSEQ * DMODEL + n * HDIM;
    float acc[4][4];
    #pragma unroll
    for (int i = 0; i < 4; i++)
        #pragma unroll
        for (int j = 0; j < 4; j++) acc[i][j] = 0.f;
    int kmax = t0 + 64; // P rows in this tile are zero beyond t0+63
    for (int k0 = 0; k0 < kmax; k0 += 32) {
        #pragma unroll
        for (int i = 0; i < 8; i++) {
            int e = tid + i * 256;
            int r = e >> 5, c = e & 31;       // P: (t=r, k=c)
            Ps[c][r] = Pp[(long)r * TSEQ + k0 + c];
        }
        #pragma unroll
        for (int i = 0; i < 8; i++) {
            int e = tid + i * 256;
            int r = e >> 6, c = e & 63;       // V: (k=r, h=c)
            Vs[r][c] = Vp[(long)(k0 + r) * DMODEL + c];
        }
        __syncthreads();
        #pragma unroll
        for (int kk = 0; kk < 32; kk++) {
            float a[4], bb[4];
            #pragma unroll
            for (int i = 0; i < 4; i++) a[i]  = Ps[kk][ty + 16 * i];
            #pragma unroll
            for (int j = 0; j < 4; j++) bb[j] = Vs[kk][tx + 16 * j];
            #pragma unroll
            for (int i = 0; i < 4; i++)
                #pragma unroll
                for (int j = 0; j < 4; j++) acc[i][j] += a[i] * bb[j];
        }
        __syncthreads();
    }
    #pragma unroll
    for (int i = 0; i < 4; i++)
        #pragma unroll
        for (int j = 0; j < 4; j++)
            O[(long)(b * TSEQ + t0 + ty + 16 * i) * DMODEL + n * HDIM + tx + 16 * j] = acc[i][j];
}

// ---------------- orchestration ----------------
extern "C" void kernel_launch(void* const* d_in, const int* in_sizes, int n_in,
                              void* d_out, int out_size) {
    const int*   ids  = (const int*)d_in[0];
    const float* wte  = (const float*)d_in[1];
    const float* wpe  = (const float*)d_in[2];
    const float* Wq   = (const float*)d_in[3];
    const float* bq   = (const float*)d_in[4];
    const float* Wk   = (const float*)d_in[5];
    const float* bk   = (const float*)d_in[6];
    const float* Wv   = (const float*)d_in[7];
    const float* bv   = (const float*)d_in[8];
    const float* Wo   = (const float*)d_in[9];
    const float* bo   = (const float*)d_in[10];
    const float* gate = (const float*)d_in[11];
    const float* ln1g = (const float*)d_in[12];
    const float* ln1b = (const float*)d_in[13];
    const float* ln2g = (const float*)d_in[14];
    const float* ln2b = (const float*)d_in[15];
    const float* w1   = (const float*)d_in[16];
    const float* b1   = (const float*)d_in[17];
    const float* w2   = (const float*)d_in[18];
    const float* b2   = (const float*)d_in[19];
    const float* skw  = (const float*)d_in[20];
    const float* skb  = (const float*)d_in[21];
    const float* lnfg = (const float*)d_in[22];
    const float* lnfb = (const float*)d_in[23];
    float* out = (float*)d_out;

    float *h, *x, *q, *k, *v, *o, *tmp, *ff, *sc, *enc, *wot, *bos;
    cudaGetSymbolAddress((void**)&h,   g_h);
    cudaGetSymbolAddress((void**)&x,   g_x);
    cudaGetSymbolAddress((void**)&q,   g_q);
    cudaGetSymbolAddress((void**)&k,   g_k);
    cudaGetSymbolAddress((void**)&v,   g_v);
    cudaGetSymbolAddress((void**)&o,   g_o);
    cudaGetSymbolAddress((void**)&tmp, g_tmp);
    cudaGetSymbolAddress((void**)&ff,  g_ff);
    cudaGetSymbolAddress((void**)&sc,  g_sc);
    cudaGetSymbolAddress((void**)&enc, g_enc);
    cudaGetSymbolAddress((void**)&wot, g_wot);
    cudaGetSymbolAddress((void**)&bos, g_bos);

    prep_wot<<<(NLAYER * DMODEL * DMODEL + 255) / 256, 256>>>(Wo, gate, wot);
    prep_bos<<<(NLAYER * DMODEL + 255) / 256, 256>>>(bo, gate, bos);
    embed_k<<<(BT * DMODEL + 255) / 256, 256>>>(ids, wte, wpe, h);

    dim3 gD(DMODEL / 128, BT / 128);   // N=1024 GEMMs
    dim3 gF(FINNER / 128, BT / 128);   // N=4096
    dim3 gV(VOCAB / 128, BT / 128);    // N=32000

    for (int i = 0; i < NLAYER; i++) {
        const float* Wq_l = Wq + (long)i * DMODEL * DMODEL;
        const float* Wk_l = Wk + (long)i * DMODEL * DMODEL;
        const float* Wv_l = Wv + (long)i * DMODEL * DMODEL;

        layernorm_k<<<BT, 256>>>(h, x, ln1g + i * DMODEL, ln1b + i * DMODEL);
        gemm128<0, true, false><<<gD, 256>>>(x, Wq_l, bq + i * DMODEL, nullptr, q,
                                             BT, DMODEL, DMODEL, DMODEL, DMODEL, DMODEL);
        gemm128<0, true, false><<<gD, 256>>>(x, Wk_l, bk + i * DMODEL, nullptr, k,
                                             BT, DMODEL, DMODEL, DMODEL, DMODEL, DMODEL);
        gemm128<0, true, false><<<gD, 256>>>(x, Wv_l, bv + i * DMODEL, nullptr, v,
                                             BT, DMODEL, DMODEL, DMODEL, DMODEL, DMODEL);

        attn_scores<<<dim3(TSEQ / 64, TSEQ / 64, BBATCH * NHEAD), 256>>>(q, k, sc);
        softmax_rows<<<dim3(TSEQ, BBATCH * NHEAD), 128>>>(sc);
        attn_pv<<<dim3(TSEQ / 64, BBATCH * NHEAD), 256>>>(sc, v, o);

        // h += o @ Wot^T + bos
        gemm128<0, true, true><<<gD, 256>>>(o, wot + (long)i * DMODEL * DMODEL,
                                            bos + i * DMODEL, h, h,
                                            BT, DMODEL, DMODEL, DMODEL, DMODEL, DMODEL);
        if (i < NLAYER / 2)
            cudaMemcpyAsync(enc + (long)i * BT * DMODEL, h,
                            (size_t)BT * DMODEL * sizeof(float), cudaMemcpyDeviceToDevice);

        layernorm_k<<<BT, 256>>>(h, x, ln2g + i * DMODEL, ln2b + i * DMODEL);
        // ff = gelu(x @ w1^T + b1)
        gemm128<2, true, false><<<gF, 256>>>(x, w1 + (long)i * FINNER * DMODEL,
                                             b1 + i * FINNER, nullptr, ff,
                                             BT, FINNER, DMODEL, DMODEL, DMODEL, FINNER);
        // h += ff @ w2^T + b2
        gemm128<0, true, true><<<gD, 256>>>(ff, w2 + (long)i * DMODEL * FINNER,
                                            b2 + i * DMODEL, h, h,
                                            BT, DMODEL, FINNER, FINNER, FINNER, DMODEL);

        if (i >= NLAYER / 2) {
            int el = NLAYER - i - 1;
            const float* sw = skw + (long)i * DMODEL * 2 * DMODEL;
            // tmp = h @ sw[:, :D]^T + skb
            gemm128<0, true, false><<<gD, 256>>>(h, sw, skb + i * DMODEL, nullptr, tmp,
                                                 BT, DMODEL, DMODEL, DMODEL, 2 * DMODEL, DMODEL);
            // h = tmp + enc[el] @ sw[:, D:]^T
            gemm128<0, false, true><<<gD, 256>>>(enc + (long)el * BT * DMODEL, sw + DMODEL,
                                                 nullptr, tmp, h,
                                                 BT, DMODEL, DMODEL, DMODEL, 2 * DMODEL, DMODEL);
        }
    }

    layernorm_k<<<BT, 256>>>(h, x, lnfg, lnfb);
    // logits = x @ wte^T
    gemm128<0, false, false><<<gV, 256>>>(x, wte, nullptr, nullptr, out,
                                          BT, VOCAB, DMODEL, DMODEL, DMODEL, VOCAB);
}

// round 3
// speedup vs baseline: 3.7755x; 3.5863x over previous
#include <cuda_runtime.h>
#include <math.h>

// Model dims
#define BBATCH 4
#define TSEQ   512
#define BT     2048      // BBATCH*TSEQ
#define DMODEL 1024
#define NHEAD  16
#define HDIM   64
#define FINNER 4096
#define VOCAB  32000
#define NLAYER 8

// ---------------- scratch (no allocations allowed) ----------------
__device__ float g_h  [BT * DMODEL];
__device__ float g_x  [BT * DMODEL];
__device__ float g_q  [BT * DMODEL];
__device__ float g_k  [BT * DMODEL];
__device__ float g_v  [BT * DMODEL];
__device__ float g_o  [BT * DMODEL];
__device__ float g_tmp[BT * DMODEL];
__device__ float g_ff [BT * FINNER];
__device__ float g_sc [(size_t)BBATCH * NHEAD * TSEQ * TSEQ]; // 67 MB
__device__ float g_enc[4 * BT * DMODEL];
__device__ float g_wot[NLAYER * DMODEL * DMODEL];             // repacked Wo*gate
__device__ float g_bos[NLAYER * DMODEL];                      // gate-reduced bo

// ---------------- prep: repack Wo with gate folded in ----------------
__global__ void prep_wot(const float* __restrict__ Wo, const float* __restrict__ gate,
                         float* __restrict__ wot) {
    long idx = (long)blockIdx.x * 256 + threadIdx.x;
    if (idx >= (long)NLAYER * DMODEL * DMODEL) return;
    int l = (int)(idx >> 20);
    int d = (int)((idx >> 10) & 1023);
    int c = (int)(idx & 1023);
    int n = c >> 6, hh = c & 63;
    wot[idx] = Wo[((long)(l * NHEAD + n)) * (DMODEL * HDIM) + (long)d * HDIM + hh]
             * gate[l * NHEAD + n];
}

__global__ void prep_bos(const float* __restrict__ bo, const float* __restrict__ gate,
                         float* __restrict__ bos) {
    int idx = blockIdx.x * 256 + threadIdx.x;
    if (idx >= NLAYER * DMODEL) return;
    int l = idx >> 10, d = idx & 1023;
    float s = 0.f;
    for (int n = 0; n < NHEAD; n++)
        s += gate[l * NHEAD + n] * bo[(long)(l * NHEAD + n) * DMODEL + d];
    bos[idx] = s;
}

// ---------------- embedding ----------------
__global__ void embed_k(const int* __restrict__ ids, const float* __restrict__ wte,
                        const float* __restrict__ wpe, float* __restrict__ h) {
    long idx = (long)blockIdx.x * 256 + threadIdx.x;
    if (idx >= (long)BT * DMODEL) return;
    int bt = (int)(idx >> 10), d = (int)(idx & 1023);
    int t = bt & (TSEQ - 1);
    h[idx] = wte[(long)ids[bt] * DMODEL + d] + wpe[(long)t * DMODEL + d];
}

// ---------------- layernorm (one block per row) ----------------
__global__ void layernorm_k(const float* __restrict__ in, float* __restrict__ out,
                            const float* __restrict__ g, const float* __restrict__ b) {
    int row = blockIdx.x;
    const float* x = in + (long)row * DMODEL;
    float* y = out + (long)row * DMODEL;
    __shared__ float red[256];
    int tid = threadIdx.x;
    float s = 0.f;
    for (int i = tid; i < DMODEL; i += 256) s += x[i];
    red[tid] = s; __syncthreads();
    for (int o = 128; o > 0; o >>= 1) { if (tid < o) red[tid] += red[tid + o]; __syncthreads(); }
    float mean = red[0] * (1.0f / DMODEL);
    __syncthreads();
    float v = 0.f;
    for (int i = tid; i < DMODEL; i += 256) { float d = x[i] - mean; v += d * d; }
    red[tid] = v; __syncthreads();
    for (int o = 128; o > 0; o >>= 1) { if (tid < o) red[tid] += red[tid + o]; __syncthreads(); }
    float inv = rsqrtf(red[0] * (1.0f / DMODEL) + 1e-5f);
    for (int i = tid; i < DMODEL; i += 256)
        y[i] = (x[i] - mean) * inv * g[i] + b[i];
}

// ---------------- tf32 tensor-core GEMM ----------------
// C[M,N] = A[M,K] * B[N,K]^T (+bias)(+res)(gelu).  BM=BN=128, BK=32.
// 256 threads = 8 warps (4m x 2n), warp tile 32x64, mma m16n8k8 tf32.
// All M/N/K are multiples of 128/128/32 — no guards.

__device__ __forceinline__ unsigned f2tf(float x) {
    unsigned r; asm("cvt.rna.tf32.f32 %0, %1;" : "=r"(r) : "f"(x)); return r;
}

__device__ __forceinline__ void mma_tf32(float c[4], unsigned a0, unsigned a1,
                                         unsigned a2, unsigned a3,
                                         unsigned b0, unsigned b1) {
    asm volatile(
        "mma.sync.aligned.m16n8k8.row.col.f32.tf32.tf32.f32 "
        "{%0,%1,%2,%3}, {%4,%5,%6,%7}, {%8,%9}, {%0,%1,%2,%3};"
        : "+f"(c[0]), "+f"(c[1]), "+f"(c[2]), "+f"(c[3])
        : "r"(a0), "r"(a1), "r"(a2), "r"(a3), "r"(b0), "r"(b1));
}

#define SMEM_STRIDE 36             // 32 + 4 pad -> conflict-free frags & STS
#define TILE_U (128 * SMEM_STRIDE) // 4608 unsigneds per buffer
#define GEMM_SMEM_BYTES (4 * TILE_U * 4)  // A[2] + B[2] = 73728 B

template<int EPI, bool BIAS, bool RES>
__global__ __launch_bounds__(256) void gemm_tf32(
    const float* __restrict__ A, const float* __restrict__ Bm,
    const float* __restrict__ bias, const float* __restrict__ res,
    float* __restrict__ C, int M, int N, int K, int lda, int ldb, int ldc) {
    extern __shared__ unsigned sm[];
    unsigned* As = sm;                 // [2][128][36]
    unsigned* Bs = sm + 2 * TILE_U;    // [2][128][36]

    int tid = threadIdx.x, lane = tid & 31, warp = tid >> 5;
    int wm = warp & 3, wn = warp >> 2;         // warp grid 4(m) x 2(n)
    int m0 = blockIdx.y * 128, n0 = blockIdx.x * 128;
    const float* Ag = A + (long)m0 * lda;
    const float* Bg = Bm + (long)n0 * ldb;

    int r_[4], c_[4];
    #pragma unroll
    for (int i = 0; i < 4; i++) { int idx = tid + i * 256; r_[i] = idx >> 3; c_[i] = (idx & 7) * 4; }

    float4 ra[4], rb[4];
    #pragma unroll
    for (int i = 0; i < 4; i++) {
        ra[i] = *(const float4*)(Ag + (long)r_[i] * lda + c_[i]);
        rb[i] = *(const float4*)(Bg + (long)r_[i] * ldb + c_[i]);
    }

    float acc[2][8][4];
    #pragma unroll
    for (int i = 0; i < 2; i++)
        #pragma unroll
        for (int j = 0; j < 8; j++)
            #pragma unroll
            for (int q = 0; q < 4; q++) acc[i][j][q] = 0.f;

    int mrow = wm * 32 + (lane >> 2);
    int nrow = wn * 64 + (lane >> 2);
    int kt = lane & 3;

    int p = 0;
    for (int k0 = 0; k0 < K; k0 += 32) {
        // stage -> smem (convert to tf32 here: 32 cvts/thread/iter)
        #pragma unroll
        for (int i = 0; i < 4; i++) {
            unsigned* a = &As[p * TILE_U + r_[i] * SMEM_STRIDE + c_[i]];
            a[0] = f2tf(ra[i].x); a[1] = f2tf(ra[i].y); a[2] = f2tf(ra[i].z); a[3] = f2tf(ra[i].w);
            unsigned* b = &Bs[p * TILE_U + r_[i] * SMEM_STRIDE + c_[i]];
            b[0] = f2tf(rb[i].x); b[1] = f2tf(rb[i].y); b[2] = f2tf(rb[i].z); b[3] = f2tf(rb[i].w);
        }
        __syncthreads();
        if (k0 + 32 < K) {
            #pragma unroll
            for (int i = 0; i < 4; i++) {
                ra[i] = *(const float4*)(Ag + (long)r_[i] * lda + k0 + 32 + c_[i]);
                rb[i] = *(const float4*)(Bg + (long)r_[i] * ldb + k0 + 32 + c_[i]);
            }
        }
        const unsigned* Ab = &As[p * TILE_U];
        const unsigned* Bb = &Bs[p * TILE_U];
        #pragma unroll
        for (int ks = 0; ks < 4; ks++) {
            int kk = ks * 8 + kt;
            unsigned af[2][4];
            #pragma unroll
            for (int i = 0; i < 2; i++) {
                const unsigned* base = Ab + (mrow + i * 16) * SMEM_STRIDE;
                af[i][0] = base[kk];
                af[i][1] = base[8 * SMEM_STRIDE + kk];
                af[i][2] = base[kk + 4];
                af[i][3] = base[8 * SMEM_STRIDE + kk + 4];
            }
            #pragma unroll
            for (int j = 0; j < 8; j++) {
                const unsigned* bb = Bb + (nrow + j * 8) * SMEM_STRIDE;
                unsigned b0 = bb[kk], b1 = bb[kk + 4];
                #pragma unroll
                for (int i = 0; i < 2; i++)
                    mma_tf32(acc[i][j], af[i][0], af[i][1], af[i][2], af[i][3], b0, b1);
            }
        }
        p ^= 1;
        // single barrier per iter: next STS targets the other buffer; the
        // buffer it overwrites was last read two iters ago, separated by
        // this iteration's sync.
    }

    // epilogue
    #pragma unroll
    for (int i = 0; i < 2; i++) {
        int m = m0 + wm * 32 + i * 16 + (lane >> 2);
        #pragma unroll
        for (int j = 0; j < 8; j++) {
            int n = n0 + wn * 64 + j * 8 + (lane & 3) * 2;
            #pragma unroll
            for (int q = 0; q < 2; q++) {
                int mm = m + q * 8;
                float v0 = acc[i][j][q * 2 + 0];
                float v1 = acc[i][j][q * 2 + 1];
                if (BIAS) { v0 += bias[n]; v1 += bias[n + 1]; }
                if (RES)  { v0 += res[(long)mm * ldc + n]; v1 += res[(long)mm * ldc + n + 1]; }
                if (EPI == 2) {
                    v0 = 0.5f * v0 * (1.0f + erff(v0 * 0.70710678118654752f));
                    v1 = 0.5f * v1 * (1.0f + erff(v1 * 0.70710678118654752f));
                }
                C[(long)mm * ldc + n]     = v0;
                C[(long)mm * ldc + n + 1] = v1;
            }
        }
    }
}

// ---------------- attention: scores = scale * Q Khead^T (causal-tile skip) ----
__global__ __launch_bounds__(256) void attn_scores(
    const float* __restrict__ Q, const float* __restrict__ Km, float* __restrict__ S) {
    int bh = blockIdx.z;
    int b = bh >> 4, n = bh & 15;
    int s0 = blockIdx.x * 64, t0 = blockIdx.y * 64;
    if (s0 > t0) return; // fully masked tile
    __shared__ float Qs[64][65];
    __shared__ float Ks[64][65];
    int tid = threadIdx.x;
    const float* Qp = Q + ((long)(b * TSEQ + t0)) * DMODEL + n * HDIM;
    const float* Kp = Km + ((long)(b * TSEQ + s0)) * DMODEL + n * HDIM;
    #pragma unroll
    for (int i = 0; i < 16; i++) {
        int e = tid + i * 256;
        int r = e >> 6, c = e & 63;
        Qs[r][c] = Qp[(long)r * DMODEL + c];
        Ks[r][c] = Kp[(long)r * DMODEL + c];
    }
    __syncthreads();
    int tx = tid & 15, ty = tid >> 4;
    float acc[4][4];
    #pragma unroll
    for (int i = 0; i < 4; i++)
        #pragma unroll
        for (int j = 0; j < 4; j++) acc[i][j] = 0.f;
    #pragma unroll 8
    for (int k = 0; k < 64; k++) {
        float a[4], bb[4];
        #pragma unroll
        for (int i = 0; i < 4; i++) a[i]  = Qs[ty + 16 * i][k];
        #pragma unroll
        for (int j = 0; j < 4; j++) bb[j] = Ks[tx + 16 * j][k];
        #pragma unroll
        for (int i = 0; i < 4; i++)
            #pragma unroll
            for (int j = 0; j < 4; j++) acc[i][j] += a[i] * bb[j];
    }
    float* Sp = S + ((long)bh * TSEQ + t0) * TSEQ + s0;
    #pragma unroll
    for (int i = 0; i < 4; i++)
        #pragma unroll
        for (int j = 0; j < 4; j++)
            Sp[(long)(ty + 16 * i) * TSEQ + tx + 16 * j] = acc[i][j] * 0.125f;
}

// ---------------- causal softmax, zero-fill s>t ----------------
__global__ void softmax_rows(float* __restrict__ S) {
    int t = blockIdx.x, bh = blockIdx.y;
    float* row = S + ((long)bh * TSEQ + t) * TSEQ;
    int len = t + 1;
    __shared__ float red[128];
    int tid = threadIdx.x;
    float mx = -1e30f;
    for (int s = tid; s < len; s += 128) mx = fmaxf(mx, row[s]);
    red[tid] = mx; __syncthreads();
    for (int o = 64; o > 0; o >>= 1) { if (tid < o) red[tid] = fmaxf(red[tid], red[tid + o]); __syncthreads(); }
    mx = red[0]; __syncthreads();
    float sum = 0.f;
    for (int s = tid; s < len; s += 128) { float e = __expf(row[s] - mx); row[s] = e; sum += e; }
    red[tid] = sum; __syncthreads();
    for (int o = 64; o > 0; o >>= 1) { if (tid < o) red[tid] += red[tid + o]; __syncthreads(); }
    float inv = 1.0f / red[0];
    for (int s = tid; s < len; s += 128) row[s] *= inv;
    for (int s = len + tid; s < TSEQ; s += 128) row[s] = 0.0f;
}

// ---------------- attention: O = P * Vhead ----------------
__global__ __launch_bounds__(256) void attn_pv(
    const float* __restrict__ P, const float* __restrict__ V, float* __restrict__ O) {
    int bh = blockIdx.y;
    int b = bh >> 4, n = bh & 15;
    int t0 = blockIdx.x * 64;
    __shared__ float Ps[32][68];
    __shared__ float Vs[32][64];
    int tid = threadIdx.x;
    int tx = tid & 15, ty = tid >> 4;
    const float* Pp = P + ((long)bh * TSEQ + t0) * TSEQ;
    const float* Vp = V + (long)b * TSEQ * DMODEL + n * HDIM;
    float acc[4][4];
    #pragma unroll
    for (int i = 0; i < 4; i++)
        #pragma unroll
        for (int j = 0; j < 4; j++) acc[i][j] = 0.f;
    int kmax = t0 + 64;
    for (int k0 = 0; k0 < kmax; k0 += 32) {
        #pragma unroll
        for (int i = 0; i < 8; i++) {
            int e = tid + i * 256;
            int r = e >> 5, c = e & 31;
            Ps[c][r] = Pp[(long)r * TSEQ + k0 + c];
        }
        #pragma unroll
        for (int i = 0; i < 8; i++) {
            int e = tid + i * 256;
            int r = e >> 6, c = e & 63;
            Vs[r][c] = Vp[(long)(k0 + r) * DMODEL + c];
        }
        __syncthreads();
        #pragma unroll
        for (int kk = 0; kk < 32; kk++) {
            float a[4], bb[4];
            #pragma unroll
            for (int i = 0; i < 4; i++) a[i]  = Ps[kk][ty + 16 * i];
            #pragma unroll
            for (int j = 0; j < 4; j++) bb[j] = Vs[kk][tx + 16 * j];
            #pragma unroll
            for (int i = 0; i < 4; i++)
                #pragma unroll
                for (int j = 0; j < 4; j++) acc[i][j] += a[i] * bb[j];
        }
        __syncthreads();
    }
    #pragma unroll
    for (int i = 0; i < 4; i++)
        #pragma unroll
        for (int j = 0; j < 4; j++)
            O[(long)(b * TSEQ + t0 + ty + 16 * i) * DMODEL + n * HDIM + tx + 16 * j] = acc[i][j];
}

// ---------------- orchestration ----------------
extern "C" void kernel_launch(void* const* d_in, const int* in_sizes, int n_in,
                              void* d_out, int out_size) {
    const int*   ids  = (const int*)d_in[0];
    const float* wte  = (const float*)d_in[1];
    const float* wpe  = (const float*)d_in[2];
    const float* Wq   = (const float*)d_in[3];
    const float* bq   = (const float*)d_in[4];
    const float* Wk   = (const float*)d_in[5];
    const float* bk   = (const float*)d_in[6];
    const float* Wv   = (const float*)d_in[7];
    const float* bv   = (const float*)d_in[8];
    const float* Wo   = (const float*)d_in[9];
    const float* bo   = (const float*)d_in[10];
    const float* gate = (const float*)d_in[11];
    const float* ln1g = (const float*)d_in[12];
    const float* ln1b = (const float*)d_in[13];
    const float* ln2g = (const float*)d_in[14];
    const float* ln2b = (const float*)d_in[15];
    const float* w1   = (const float*)d_in[16];
    const float* b1   = (const float*)d_in[17];
    const float* w2   = (const float*)d_in[18];
    const float* b2   = (const float*)d_in[19];
    const float* skw  = (const float*)d_in[20];
    const float* skb  = (const float*)d_in[21];
    const float* lnfg = (const float*)d_in[22];
    const float* lnfb = (const float*)d_in[23];
    float* out = (float*)d_out;

    float *h, *x, *q, *k, *v, *o, *tmp, *ff, *sc, *enc, *wot, *bos;
    cudaGetSymbolAddress((void**)&h,   g_h);
    cudaGetSymbolAddress((void**)&x,   g_x);
    cudaGetSymbolAddress((void**)&q,   g_q);
    cudaGetSymbolAddress((void**)&k,   g_k);
    cudaGetSymbolAddress((void**)&v,   g_v);
    cudaGetSymbolAddress((void**)&o,   g_o);
    cudaGetSymbolAddress((void**)&tmp, g_tmp);
    cudaGetSymbolAddress((void**)&ff,  g_ff);
    cudaGetSymbolAddress((void**)&sc,  g_sc);
    cudaGetSymbolAddress((void**)&enc, g_enc);
    cudaGetSymbolAddress((void**)&wot, g_wot);
    cudaGetSymbolAddress((void**)&bos, g_bos);

    // allow >48KB dynamic smem on every gemm instantiation (idempotent)
    cudaFuncSetAttribute(gemm_tf32<0, true,  false>, cudaFuncAttributeMaxDynamicSharedMemorySize, GEMM_SMEM_BYTES);
    cudaFuncSetAttribute(gemm_tf32<0, true,  true >, cudaFuncAttributeMaxDynamicSharedMemorySize, GEMM_SMEM_BYTES);
    cudaFuncSetAttribute(gemm_tf32<2, true,  false>, cudaFuncAttributeMaxDynamicSharedMemorySize, GEMM_SMEM_BYTES);
    cudaFuncSetAttribute(gemm_tf32<0, false, true >, cudaFuncAttributeMaxDynamicSharedMemorySize, GEMM_SMEM_BYTES);
    cudaFuncSetAttribute(gemm_tf32<0, false, false>, cudaFuncAttributeMaxDynamicSharedMemorySize, GEMM_SMEM_BYTES);

    prep_wot<<<(NLAYER * DMODEL * DMODEL + 255) / 256, 256>>>(Wo, gate, wot);
    prep_bos<<<(NLAYER * DMODEL + 255) / 256, 256>>>(bo, gate, bos);
    embed_k<<<(BT * DMODEL + 255) / 256, 256>>>(ids, wte, wpe, h);

    dim3 gD(DMODEL / 128, BT / 128);   // N=1024 GEMMs
    dim3 gF(FINNER / 128, BT / 128);   // N=4096
    dim3 gV(VOCAB / 128, BT / 128);    // N=32000

    for (int i = 0; i < NLAYER; i++) {
        const float* Wq_l = Wq + (long)i * DMODEL * DMODEL;
        const float* Wk_l = Wk + (long)i * DMODEL * DMODEL;
        const float* Wv_l = Wv + (long)i * DMODEL * DMODEL;

        layernorm_k<<<BT, 256>>>(h, x, ln1g + i * DMODEL, ln1b + i * DMODEL);
        gemm_tf32<0, true, false><<<gD, 256, GEMM_SMEM_BYTES>>>(
            x, Wq_l, bq + i * DMODEL, nullptr, q, BT, DMODEL, DMODEL, DMODEL, DMODEL, DMODEL);
        gemm_tf32<0, true, false><<<gD, 256, GEMM_SMEM_BYTES>>>(
            x, Wk_l, bk + i * DMODEL, nullptr, k, BT, DMODEL, DMODEL, DMODEL, DMODEL, DMODEL);
        gemm_tf32<0, true, false><<<gD, 256, GEMM_SMEM_BYTES>>>(
            x, Wv_l, bv + i * DMODEL, nullptr, v, BT, DMODEL, DMODEL, DMODEL, DMODEL, DMODEL);

        attn_scores<<<dim3(TSEQ / 64, TSEQ / 64, BBATCH * NHEAD), 256>>>(q, k, sc);
        softmax_rows<<<dim3(TSEQ, BBATCH * NHEAD), 128>>>(sc);
        attn_pv<<<dim3(TSEQ / 64, BBATCH * NHEAD), 256>>>(sc, v, o);

        // h += o @ Wot^T + bos
        gemm_tf32<0, true, true><<<gD, 256, GEMM_SMEM_BYTES>>>(
            o, wot + (long)i * DMODEL * DMODEL, bos + i * DMODEL, h, h,
            BT, DMODEL, DMODEL, DMODEL, DMODEL, DMODEL);
        if (i < NLAYER / 2)
            cudaMemcpyAsync(enc + (long)i * BT * DMODEL, h,
                            (size_t)BT * DMODEL * sizeof(float), cudaMemcpyDeviceToDevice);

        layernorm_k<<<BT, 256>>>(h, x, ln2g + i * DMODEL, ln2b + i * DMODEL);
        // ff = gelu(x @ w1^T + b1)
        gemm_tf32<2, true, false><<<gF, 256, GEMM_SMEM_BYTES>>>(
            x, w1 + (long)i * FINNER * DMODEL, b1 + i * FINNER, nullptr, ff,
            BT, FINNER, DMODEL, DMODEL, DMODEL, FINNER);
        // h += ff @ w2^T + b2
        gemm_tf32<0, true, true><<<gD, 256, GEMM_SMEM_BYTES>>>(
            ff, w2 + (long)i * DMODEL * FINNER, b2 + i * DMODEL, h, h,
            BT, DMODEL, FINNER, FINNER, FINNER, DMODEL);

        if (i >= NLAYER / 2) {
            int el = NLAYER - i - 1;
            const float* sw = skw + (long)i * DMODEL * 2 * DMODEL;
            // tmp = h @ sw[:, :D]^T + skb
            gemm_tf32<0, true, false><<<gD, 256, GEMM_SMEM_BYTES>>>(
                h, sw, skb + i * DMODEL, nullptr, tmp,
                BT, DMODEL, DMODEL, DMODEL, 2 * DMODEL, DMODEL);
            // h = tmp + enc[el] @ sw[:, D:]^T
            gemm_tf32<0, false, true><<<gD, 256, GEMM_SMEM_BYTES>>>(
                enc + (long)el * BT * DMODEL, sw + DMODEL, nullptr, tmp, h,
                BT, DMODEL, DMODEL, DMODEL, 2 * DMODEL, DMODEL);
        }
    }

    layernorm_k<<<BT, 256>>>(h, x, lnfg, lnfb);
    // logits = x @ wte^T
    gemm_tf32<0, false, false><<<gV, 256, GEMM_SMEM_BYTES>>>(
        x, wte, nullptr, nullptr, out, BT, VOCAB, DMODEL, DMODEL, DMODEL, VOCAB);
}

// round 4
// speedup vs baseline: 3.7833x; 1.0021x over previous
#include <cuda_runtime.h>
#include <math.h>

// Model dims
#define BBATCH 4
#define TSEQ   512
#define BT     2048      // BBATCH*TSEQ
#define DMODEL 1024
#define NHEAD  16
#define HDIM   64
#define FINNER 4096
#define VOCAB  32000
#define NLAYER 8

// ---------------- scratch (no allocations allowed) ----------------
__device__ float g_h  [BT * DMODEL];
__device__ float g_x  [BT * DMODEL];
__device__ float g_q  [BT * DMODEL];
__device__ float g_k  [BT * DMODEL];
__device__ float g_v  [BT * DMODEL];
__device__ float g_o  [BT * DMODEL];
__device__ float g_tmp[BT * DMODEL];
__device__ float g_ff [BT * FINNER];
__device__ float g_sc [(size_t)BBATCH * NHEAD * TSEQ * TSEQ]; // 67 MB
__device__ float g_enc[4 * BT * DMODEL];
__device__ float g_wot[NLAYER * DMODEL * DMODEL];             // repacked Wo*gate
__device__ float g_bos[NLAYER * DMODEL];                      // gate-reduced bo

// ---------------- prep: repack Wo with gate folded in ----------------
__global__ void prep_wot(const float* __restrict__ Wo, const float* __restrict__ gate,
                         float* __restrict__ wot) {
    long idx = (long)blockIdx.x * 256 + threadIdx.x;
    if (idx >= (long)NLAYER * DMODEL * DMODEL) return;
    int l = (int)(idx >> 20);
    int d = (int)((idx >> 10) & 1023);
    int c = (int)(idx & 1023);
    int n = c >> 6, hh = c & 63;
    wot[idx] = Wo[((long)(l * NHEAD + n)) * (DMODEL * HDIM) + (long)d * HDIM + hh]
             * gate[l * NHEAD + n];
}

__global__ void prep_bos(const float* __restrict__ bo, const float* __restrict__ gate,
                         float* __restrict__ bos) {
    int idx = blockIdx.x * 256 + threadIdx.x;
    if (idx >= NLAYER * DMODEL) return;
    int l = idx >> 10, d = idx & 1023;
    float s = 0.f;
    for (int n = 0; n < NHEAD; n++)
        s += gate[l * NHEAD + n] * bo[(long)(l * NHEAD + n) * DMODEL + d];
    bos[idx] = s;
}

// ---------------- embedding ----------------
__global__ void embed_k(const int* __restrict__ ids, const float* __restrict__ wte,
                        const float* __restrict__ wpe, float* __restrict__ h) {
    long idx = (long)blockIdx.x * 256 + threadIdx.x;
    if (idx >= (long)BT * DMODEL) return;
    int bt = (int)(idx >> 10), d = (int)(idx & 1023);
    int t = bt & (TSEQ - 1);
    h[idx] = wte[(long)ids[bt] * DMODEL + d] + wpe[(long)t * DMODEL + d];
}

// ---------------- layernorm (one block per row) ----------------
__global__ void layernorm_k(const float* __restrict__ in, float* __restrict__ out,
                            const float* __restrict__ g, const float* __restrict__ b) {
    int row = blockIdx.x;
    const float* x = in + (long)row * DMODEL;
    float* y = out + (long)row * DMODEL;
    __shared__ float red[256];
    int tid = threadIdx.x;
    float s = 0.f;
    for (int i = tid; i < DMODEL; i += 256) s += x[i];
    red[tid] = s; __syncthreads();
    for (int o = 128; o > 0; o >>= 1) { if (tid < o) red[tid] += red[tid + o]; __syncthreads(); }
    float mean = red[0] * (1.0f / DMODEL);
    __syncthreads();
    float v = 0.f;
    for (int i = tid; i < DMODEL; i += 256) { float d = x[i] - mean; v += d * d; }
    red[tid] = v; __syncthreads();
    for (int o = 128; o > 0; o >>= 1) { if (tid < o) red[tid] += red[tid + o]; __syncthreads(); }
    float inv = rsqrtf(red[0] * (1.0f / DMODEL) + 1e-5f);
    for (int i = tid; i < DMODEL; i += 256)
        y[i] = (x[i] - mean) * inv * g[i] + b[i];
}

// ---------------- tf32 tensor-core GEMM ----------------
// C[M,N] = A[M,K] * B[N,K]^T (+bias)(+res)(gelu).  BM=BN=128, BK=32.
// 256 threads = 8 warps (4m x 2n), warp tile 32x64, mma m16n8k8 tf32.
// All M/N/K are multiples of 128/128/32 — no guards.

__device__ __forceinline__ unsigned f2tf(float x) {
    unsigned r; asm("cvt.rna.tf32.f32 %0, %1;" : "=r"(r) : "f"(x)); return r;
}

__device__ __forceinline__ void mma_tf32(float c[4], unsigned a0, unsigned a1,
                                         unsigned a2, unsigned a3,
                                         unsigned b0, unsigned b1) {
    asm volatile(
        "mma.sync.aligned.m16n8k8.row.col.f32.tf32.tf32.f32 "
        "{%0,%1,%2,%3}, {%4,%5,%6,%7}, {%8,%9}, {%0,%1,%2,%3};"
        : "+f"(c[0]), "+f"(c[1]), "+f"(c[2]), "+f"(c[3])
        : "r"(a0), "r"(a1), "r"(a2), "r"(a3), "r"(b0), "r"(b1));
}

#define SMEM_STRIDE 36             // 32 + 4 pad -> conflict-free frags & STS
#define TILE_U (128 * SMEM_STRIDE) // 4608 unsigneds per buffer
#define GEMM_SMEM_BYTES (4 * TILE_U * 4)  // A[2] + B[2] = 73728 B

template<int EPI, bool BIAS, bool RES>
__global__ __launch_bounds__(256) void gemm_tf32(
    const float* __restrict__ A, const float* __restrict__ Bm,
    const float* __restrict__ bias, const float* __restrict__ res,
    float* __restrict__ C, int M, int N, int K, int lda, int ldb, int ldc) {
    extern __shared__ unsigned sm[];
    unsigned* As = sm;                 // [2][128][36]
    unsigned* Bs = sm + 2 * TILE_U;    // [2][128][36]

    int tid = threadIdx.x, lane = tid & 31, warp = tid >> 5;
    int wm = warp & 3, wn = warp >> 2;         // warp grid 4(m) x 2(n)
    int m0 = blockIdx.y * 128, n0 = blockIdx.x * 128;
    const float* Ag = A + (long)m0 * lda;
    const float* Bg = Bm + (long)n0 * ldb;

    int r_[4], c_[4];
    #pragma unroll
    for (int i = 0; i < 4; i++) { int idx = tid + i * 256; r_[i] = idx >> 3; c_[i] = (idx & 7) * 4; }

    float4 ra[4], rb[4];
    #pragma unroll
    for (int i = 0; i < 4; i++) {
        ra[i] = *(const float4*)(Ag + (long)r_[i] * lda + c_[i]);
        rb[i] = *(const float4*)(Bg + (long)r_[i] * ldb + c_[i]);
    }

    float acc[2][8][4];
    #pragma unroll
    for (int i = 0; i < 2; i++)
        #pragma unroll
        for (int j = 0; j < 8; j++)
            #pragma unroll
            for (int q = 0; q < 4; q++) acc[i][j][q] = 0.f;

    int mrow = wm * 32 + (lane >> 2);
    int nrow = wn * 64 + (lane >> 2);
    int kt = lane & 3;

    int p = 0;
    for (int k0 = 0; k0 < K; k0 += 32) {
        // stage -> smem (convert to tf32 here: 32 cvts/thread/iter)
        #pragma unroll
        for (int i = 0; i < 4; i++) {
            unsigned* a = &As[p * TILE_U + r_[i] * SMEM_STRIDE + c_[i]];
            a[0] = f2tf(ra[i].x); a[1] = f2tf(ra[i].y); a[2] = f2tf(ra[i].z); a[3] = f2tf(ra[i].w);
            unsigned* b = &Bs[p * TILE_U + r_[i] * SMEM_STRIDE + c_[i]];
            b[0] = f2tf(rb[i].x); b[1] = f2tf(rb[i].y); b[2] = f2tf(rb[i].z); b[3] = f2tf(rb[i].w);
        }
        __syncthreads();
        if (k0 + 32 < K) {
            #pragma unroll
            for (int i = 0; i < 4; i++) {
                ra[i] = *(const float4*)(Ag + (long)r_[i] * lda + k0 + 32 + c_[i]);
                rb[i] = *(const float4*)(Bg + (long)r_[i] * ldb + k0 + 32 + c_[i]);
            }
        }
        const unsigned* Ab = &As[p * TILE_U];
        const unsigned* Bb = &Bs[p * TILE_U];
        #pragma unroll
        for (int ks = 0; ks < 4; ks++) {
            int kk = ks * 8 + kt;
            unsigned af[2][4];
            #pragma unroll
            for (int i = 0; i < 2; i++) {
                const unsigned* base = Ab + (mrow + i * 16) * SMEM_STRIDE;
                af[i][0] = base[kk];
                af[i][1] = base[8 * SMEM_STRIDE + kk];
                af[i][2] = base[kk + 4];
                af[i][3] = base[8 * SMEM_STRIDE + kk + 4];
            }
            #pragma unroll
            for (int j = 0; j < 8; j++) {
                const unsigned* bb = Bb + (nrow + j * 8) * SMEM_STRIDE;
                unsigned b0 = bb[kk], b1 = bb[kk + 4];
                #pragma unroll
                for (int i = 0; i < 2; i++)
                    mma_tf32(acc[i][j], af[i][0], af[i][1], af[i][2], af[i][3], b0, b1);
            }
        }
        p ^= 1;
        // single barrier per iter: next STS targets the other buffer; the
        // buffer it overwrites was last read two iters ago, separated by
        // this iteration's sync.
    }

    // epilogue
    #pragma unroll
    for (int i = 0; i < 2; i++) {
        int m = m0 + wm * 32 + i * 16 + (lane >> 2);
        #pragma unroll
        for (int j = 0; j < 8; j++) {
            int n = n0 + wn * 64 + j * 8 + (lane & 3) * 2;
            #pragma unroll
            for (int q = 0; q < 2; q++) {
                int mm = m + q * 8;
                float v0 = acc[i][j][q * 2 + 0];
                float v1 = acc[i][j][q * 2 + 1];
                if (BIAS) { v0 += bias[n]; v1 += bias[n + 1]; }
                if (RES)  { v0 += res[(long)mm * ldc + n]; v1 += res[(long)mm * ldc + n + 1]; }
                if (EPI == 2) {
                    v0 = 0.5f * v0 * (1.0f + erff(v0 * 0.70710678118654752f));
                    v1 = 0.5f * v1 * (1.0f + erff(v1 * 0.70710678118654752f));
                }
                C[(long)mm * ldc + n]     = v0;
                C[(long)mm * ldc + n + 1] = v1;
            }
        }
    }
}

// ---------------- attention: scores = scale * Q Khead^T (causal-tile skip) ----
__global__ __launch_bounds__(256) void attn_scores(
    const float* __restrict__ Q, const float* __restrict__ Km, float* __restrict__ S) {
    int bh = blockIdx.z;
    int b = bh >> 4, n = bh & 15;
    int s0 = blockIdx.x * 64, t0 = blockIdx.y * 64;
    if (s0 > t0) return; // fully masked tile
    __shared__ float Qs[64][65];
    __shared__ float Ks[64][65];
    int tid = threadIdx.x;
    const float* Qp = Q + ((long)(b * TSEQ + t0)) * DMODEL + n * HDIM;
    const float* Kp = Km + ((long)(b * TSEQ + s0)) * DMODEL + n * HDIM;
    #pragma unroll
    for (int i = 0; i < 16; i++) {
        int e = tid + i * 256;
        int r = e >> 6, c = e & 63;
        Qs[r][c] = Qp[(long)r * DMODEL + c];
        Ks[r][c] = Kp[(long)r * DMODEL + c];
    }
    __syncthreads();
    int tx = tid & 15, ty = tid >> 4;
    float acc[4][4];
    #pragma unroll
    for (int i = 0; i < 4; i++)
        #pragma unroll
        for (int j = 0; j < 4; j++) acc[i][j] = 0.f;
    #pragma unroll 8
    for (int k = 0; k < 64; k++) {
        float a[4], bb[4];
        #pragma unroll
        for (int i = 0; i < 4; i++) a[i]  = Qs[ty + 16 * i][k];
        #pragma unroll
        for (int j = 0; j < 4; j++) bb[j] = Ks[tx + 16 * j][k];
        #pragma unroll
        for (int i = 0; i < 4; i++)
            #pragma unroll
            for (int j = 0; j < 4; j++) acc[i][j] += a[i] * bb[j];
    }
    float* Sp = S + ((long)bh * TSEQ + t0) * TSEQ + s0;
    #pragma unroll
    for (int i = 0; i < 4; i++)
        #pragma unroll
        for (int j = 0; j < 4; j++)
            Sp[(long)(ty + 16 * i) * TSEQ + tx + 16 * j] = acc[i][j] * 0.125f;
}

// ---------------- causal softmax, zero-fill s>t ----------------
__global__ void softmax_rows(float* __restrict__ S) {
    int t = blockIdx.x, bh = blockIdx.y;
    float* row = S + ((long)bh * TSEQ + t) * TSEQ;
    int len = t + 1;
    __shared__ float red[128];
    int tid = threadIdx.x;
    float mx = -1e30f;
    for (int s = tid; s < len; s += 128) mx = fmaxf(mx, row[s]);
    red[tid] = mx; __syncthreads();
    for (int o = 64; o > 0; o >>= 1) { if (tid < o) red[tid] = fmaxf(red[tid], red[tid + o]); __syncthreads(); }
    mx = red[0]; __syncthreads();
    float sum = 0.f;
    for (int s = tid; s < len; s += 128) { float e = __expf(row[s] - mx); row[s] = e; sum += e; }
    red[tid] = sum; __syncthreads();
    for (int o = 64; o > 0; o >>= 1) { if (tid < o) red[tid] += red[tid + o]; __syncthreads(); }
    float inv = 1.0f / red[0];
    for (int s = tid; s < len; s += 128) row[s] *= inv;
    for (int s = len + tid; s < TSEQ; s += 128) row[s] = 0.0f;
}

// ---------------- attention: O = P * Vhead ----------------
__global__ __launch_bounds__(256) void attn_pv(
    const float* __restrict__ P, const float* __restrict__ V, float* __restrict__ O) {
    int bh = blockIdx.y;
    int b = bh >> 4, n = bh & 15;
    int t0 = blockIdx.x * 64;
    __shared__ float Ps[32][68];
    __shared__ float Vs[32][64];
    int tid = threadIdx.x;
    int tx = tid & 15, ty = tid >> 4;
    const float* Pp = P + ((long)bh * TSEQ + t0) * TSEQ;
    const float* Vp = V + (long)b * TSEQ * DMODEL + n * HDIM;
    float acc[4][4];
    #pragma unroll
    for (int i = 0; i < 4; i++)
        #pragma unroll
        for (int j = 0; j < 4; j++) acc[i][j] = 0.f;
    int kmax = t0 + 64;
    for (int k0 = 0; k0 < kmax; k0 += 32) {
        #pragma unroll
        for (int i = 0; i < 8; i++) {
            int e = tid + i * 256;
            int r = e >> 5, c = e & 31;
            Ps[c][r] = Pp[(long)r * TSEQ + k0 + c];
        }
        #pragma unroll
        for (int i = 0; i < 8; i++) {
            int e = tid + i * 256;
            int r = e >> 6, c = e & 63;
            Vs[r][c] = Vp[(long)(k0 + r) * DMODEL + c];
        }
        __syncthreads();
        #pragma unroll
        for (int kk = 0; kk < 32; kk++) {
            float a[4], bb[4];
            #pragma unroll
            for (int i = 0; i < 4; i++) a[i]  = Ps[kk][ty + 16 * i];
            #pragma unroll
            for (int j = 0; j < 4; j++) bb[j] = Vs[kk][tx + 16 * j];
            #pragma unroll
            for (int i = 0; i < 4; i++)
                #pragma unroll
                for (int j = 0; j < 4; j++) acc[i][j] += a[i] * bb[j];
        }
        __syncthreads();
    }
    #pragma unroll
    for (int i = 0; i < 4; i++)
        #pragma unroll
        for (int j = 0; j < 4; j++)
            O[(long)(b * TSEQ + t0 + ty + 16 * i) * DMODEL + n * HDIM + tx + 16 * j] = acc[i][j];
}

// ---------------- orchestration ----------------
extern "C" void kernel_launch(void* const* d_in, const int* in_sizes, int n_in,
                              void* d_out, int out_size) {
    const int*   ids  = (const int*)d_in[0];
    const float* wte  = (const float*)d_in[1];
    const float* wpe  = (const float*)d_in[2];
    const float* Wq   = (const float*)d_in[3];
    const float* bq   = (const float*)d_in[4];
    const float* Wk   = (const float*)d_in[5];
    const float* bk   = (const float*)d_in[6];
    const float* Wv   = (const float*)d_in[7];
    const float* bv   = (const float*)d_in[8];
    const float* Wo   = (const float*)d_in[9];
    const float* bo   = (const float*)d_in[10];
    const float* gate = (const float*)d_in[11];
    const float* ln1g = (const float*)d_in[12];
    const float* ln1b = (const float*)d_in[13];
    const float* ln2g = (const float*)d_in[14];
    const float* ln2b = (const float*)d_in[15];
    const float* w1   = (const float*)d_in[16];
    const float* b1   = (const float*)d_in[17];
    const float* w2   = (const float*)d_in[18];
    const float* b2   = (const float*)d_in[19];
    const float* skw  = (const float*)d_in[20];
    const float* skb  = (const float*)d_in[21];
    const float* lnfg = (const float*)d_in[22];
    const float* lnfb = (const float*)d_in[23];
    float* out = (float*)d_out;

    float *h, *x, *q, *k, *v, *o, *tmp, *ff, *sc, *enc, *wot, *bos;
    cudaGetSymbolAddress((void**)&h,   g_h);
    cudaGetSymbolAddress((void**)&x,   g_x);
    cudaGetSymbolAddress((void**)&q,   g_q);
    cudaGetSymbolAddress((void**)&k,   g_k);
    cudaGetSymbolAddress((void**)&v,   g_v);
    cudaGetSymbolAddress((void**)&o,   g_o);
    cudaGetSymbolAddress((void**)&tmp, g_tmp);
    cudaGetSymbolAddress((void**)&ff,  g_ff);
    cudaGetSymbolAddress((void**)&sc,  g_sc);
    cudaGetSymbolAddress((void**)&enc, g_enc);
    cudaGetSymbolAddress((void**)&wot, g_wot);
    cudaGetSymbolAddress((void**)&bos, g_bos);

    // allow >48KB dynamic smem on every gemm instantiation (idempotent)
    cudaFuncSetAttribute(gemm_tf32<0, true,  false>, cudaFuncAttributeMaxDynamicSharedMemorySize, GEMM_SMEM_BYTES);
    cudaFuncSetAttribute(gemm_tf32<0, true,  true >, cudaFuncAttributeMaxDynamicSharedMemorySize, GEMM_SMEM_BYTES);
    cudaFuncSetAttribute(gemm_tf32<2, true,  false>, cudaFuncAttributeMaxDynamicSharedMemorySize, GEMM_SMEM_BYTES);
    cudaFuncSetAttribute(gemm_tf32<0, false, true >, cudaFuncAttributeMaxDynamicSharedMemorySize, GEMM_SMEM_BYTES);
    cudaFuncSetAttribute(gemm_tf32<0, false, false>, cudaFuncAttributeMaxDynamicSharedMemorySize, GEMM_SMEM_BYTES);

    prep_wot<<<(NLAYER * DMODEL * DMODEL + 255) / 256, 256>>>(Wo, gate, wot);
    prep_bos<<<(NLAYER * DMODEL + 255) / 256, 256>>>(bo, gate, bos);
    embed_k<<<(BT * DMODEL + 255) / 256, 256>>>(ids, wte, wpe, h);

    dim3 gD(DMODEL / 128, BT / 128);   // N=1024 GEMMs
    dim3 gF(FINNER / 128, BT / 128);   // N=4096
    dim3 gV(VOCAB / 128, BT / 128);    // N=32000

    for (int i = 0; i < NLAYER; i++) {
        const float* Wq_l = Wq + (long)i * DMODEL * DMODEL;
        const float* Wk_l = Wk + (long)i * DMODEL * DMODEL;
        const float* Wv_l = Wv + (long)i * DMODEL * DMODEL;

        layernorm_k<<<BT, 256>>>(h, x, ln1g + i * DMODEL, ln1b + i * DMODEL);
        gemm_tf32<0, true, false><<<gD, 256, GEMM_SMEM_BYTES>>>(
            x, Wq_l, bq + i * DMODEL, nullptr, q, BT, DMODEL, DMODEL, DMODEL, DMODEL, DMODEL);
        gemm_tf32<0, true, false><<<gD, 256, GEMM_SMEM_BYTES>>>(
            x, Wk_l, bk + i * DMODEL, nullptr, k, BT, DMODEL, DMODEL, DMODEL, DMODEL, DMODEL);
        gemm_tf32<0, true, false><<<gD, 256, GEMM_SMEM_BYTES>>>(
            x, Wv_l, bv + i * DMODEL, nullptr, v, BT, DMODEL, DMODEL, DMODEL, DMODEL, DMODEL);

        attn_scores<<<dim3(TSEQ / 64, TSEQ / 64, BBATCH * NHEAD), 256>>>(q, k, sc);
        softmax_rows<<<dim3(TSEQ, BBATCH * NHEAD), 128>>>(sc);
        attn_pv<<<dim3(TSEQ / 64, BBATCH * NHEAD), 256>>>(sc, v, o);

        // h += o @ Wot^T + bos
        gemm_tf32<0, true, true><<<gD, 256, GEMM_SMEM_BYTES>>>(
            o, wot + (long)i * DMODEL * DMODEL, bos + i * DMODEL, h, h,
            BT, DMODEL, DMODEL, DMODEL, DMODEL, DMODEL);
        if (i < NLAYER / 2)
            cudaMemcpyAsync(enc + (long)i * BT * DMODEL, h,
                            (size_t)BT * DMODEL * sizeof(float), cudaMemcpyDeviceToDevice);

        layernorm_k<<<BT, 256>>>(h, x, ln2g + i * DMODEL, ln2b + i * DMODEL);
        // ff = gelu(x @ w1^T + b1)
        gemm_tf32<2, true, false><<<gF, 256, GEMM_SMEM_BYTES>>>(
            x, w1 + (long)i * FINNER * DMODEL, b1 + i * FINNER, nullptr, ff,
            BT, FINNER, DMODEL, DMODEL, DMODEL, FINNER);
        // h += ff @ w2^T + b2
        gemm_tf32<0, true, true><<<gD, 256, GEMM_SMEM_BYTES>>>(
            ff, w2 + (long)i * DMODEL * FINNER, b2 + i * DMODEL, h, h,
            BT, DMODEL, FINNER, FINNER, FINNER, DMODEL);

        if (i >= NLAYER / 2) {
            int el = NLAYER - i - 1;
            const float* sw = skw + (long)i * DMODEL * 2 * DMODEL;
            // tmp = h @ sw[:, :D]^T + skb
            gemm_tf32<0, true, false><<<gD, 256, GEMM_SMEM_BYTES>>>(
                h, sw, skb + i * DMODEL, nullptr, tmp,
                BT, DMODEL, DMODEL, DMODEL, 2 * DMODEL, DMODEL);
            // h = tmp + enc[el] @ sw[:, D:]^T
            gemm_tf32<0, false, true><<<gD, 256, GEMM_SMEM_BYTES>>>(
                enc + (long)el * BT * DMODEL, sw + DMODEL, nullptr, tmp, h,
                BT, DMODEL, DMODEL, DMODEL, 2 * DMODEL, DMODEL);
        }
    }

    layernorm_k<<<BT, 256>>>(h, x, lnfg, lnfb);
    // logits = x @ wte^T
    gemm_tf32<0, false, false><<<gV, 256, GEMM_SMEM_BYTES>>>(
        x, wte, nullptr, nullptr, out, BT, VOCAB, DMODEL, DMODEL, DMODEL, VOCAB);
}